// round 6
// baseline (speedup 1.0000x reference)
#include <cuda_runtime.h>
#include <stdint.h>

constexpr int THREADS = 128;
constexpr float HSTEP  = 0.05f;     // 0.5 * dt_eff
constexpr float DT_EFF = 0.1f;
constexpr float CMU_H  = 0.00125f;  // 0.5 * h * FRICTION_SCALE
constexpr float TWO_PI     = 6.2831853071795864769f;
constexpr float INV_TWO_PI = 0.15915494309189533577f;

// ---------------- helpers ----------------
__device__ __forceinline__ uint32_t bf2(float lo, float hi){
    uint32_t r; asm("cvt.rn.bf16x2.f32 %0, %1, %2;" : "=r"(r) : "f"(hi), "f"(lo)); return r;
}
__device__ __forceinline__ void split2(float x0, float x1, uint32_t& hi, uint32_t& lo){
    hi = bf2(x0, x1);
    float h0 = __uint_as_float(hi << 16);
    float h1 = __uint_as_float(hi & 0xFFFF0000u);
    lo = bf2(x0 - h0, x1 - h1);
}
__device__ __forceinline__ uint32_t pkh(float lo, float hi){
    uint32_t r; asm("cvt.rn.f16x2.f32 %0, %1, %2;" : "=r"(r) : "f"(hi), "f"(lo)); return r;
}
__device__ __forceinline__ uint32_t hadd2(uint32_t a, uint32_t b){
    uint32_t r; asm("add.rn.f16x2 %0, %1, %2;" : "=r"(r) : "r"(a), "r"(b)); return r;
}
__device__ __forceinline__ uint32_t hmul2(uint32_t a, uint32_t b){
    uint32_t r; asm("mul.rn.f16x2 %0, %1, %2;" : "=r"(r) : "r"(a), "r"(b)); return r;
}
__device__ __forceinline__ uint32_t hfma2(uint32_t a, uint32_t b, uint32_t c){
    uint32_t r; asm("fma.rn.f16x2 %0, %1, %2, %3;" : "=r"(r) : "r"(a), "r"(b), "r"(c)); return r;
}
__device__ __forceinline__ uint32_t htanh2(uint32_t a){
    uint32_t r; asm("tanh.approx.f16x2 %0, %1;" : "=r"(r) : "r"(a)); return r;
}
__device__ __forceinline__ uint32_t hneg2(uint32_t a){
    uint32_t r; asm("neg.f16x2 %0, %1;" : "=r"(r) : "r"(a)); return r;
}
__device__ __forceinline__ float2 h2f2(uint32_t h){
    float2 r;
    asm("{ .reg .f16 lo, hi; mov.b32 {lo, hi}, %2; cvt.f32.f16 %0, lo; cvt.f32.f16 %1, hi; }"
        : "=f"(r.x), "=f"(r.y) : "r"(h));
    return r;
}
// bf16 x bf16 -> f32 accum
__device__ __forceinline__ void mma(float* c, uint32_t a0, uint32_t a1, uint32_t a2, uint32_t a3,
                                    uint32_t b0, uint32_t b1){
    asm("mma.sync.aligned.m16n8k16.row.col.f32.bf16.bf16.f32 "
        "{%0,%1,%2,%3}, {%4,%5,%6,%7}, {%8,%9}, {%0,%1,%2,%3};"
        : "+f"(c[0]), "+f"(c[1]), "+f"(c[2]), "+f"(c[3])
        : "r"(a0), "r"(a1), "r"(a2), "r"(a3), "r"(b0), "r"(b1));
}
// f16 x f16 -> f16 accum (2x rate, 2-reg C)
__device__ __forceinline__ void mmah(uint32_t* c, uint32_t a0, uint32_t a1, uint32_t a2, uint32_t a3,
                                     uint32_t b0, uint32_t b1){
    asm("mma.sync.aligned.m16n8k16.row.col.f16.f16.f16.f16 "
        "{%0,%1}, {%2,%3,%4,%5}, {%6,%7}, {%0,%1};"
        : "+r"(c[0]), "+r"(c[1])
        : "r"(a0), "r"(a1), "r"(a2), "r"(a3), "r"(b0), "r"(b1));
}

// =====================================================================
// Warp owns 16 rows, full 64 cols. Thread (g=lane>>2, m=lane&3) owns rows
// {g, g+8}, cols 8s+2m+e; state idx = rr*16 + 2s + e. Matches mma A/C
// fragment layouts; main loop is barrier-free.
// =====================================================================
__global__ void __launch_bounds__(THREADS, 3)
leapfrog_r6_kernel(const float* __restrict__ x_in, const float* __restrict__ v_in,
                   const float* __restrict__ f_in, const float* __restrict__ U_in,
                   const float* __restrict__ W_in, const float* __restrict__ Wf_in,
                   const float* __restrict__ bf_in, const int* __restrict__ steps_ptr,
                   float* __restrict__ out, int Btot)
{
    __shared__ uint4 sWf[8 * 32 * 5];        // gate B-frags f16 [kt][lane][4j + pad]
    __shared__ uint4 sU[32 * 9];             // U frags [lane][2*kt + (0:hi,1:lo)]
    __shared__ uint4 sW[32 * 9];             // W frags [lane][2*j  + (0:hi,1:lo)]
    __shared__ uint32_t sB16[32];            // bias f16x2 [nt*4+m]
    __shared__ float sHF[128 * 34];          // h*force per thread, stride 34

    const int tid = threadIdx.x, wid = tid >> 5, lane = tid & 31;
    const int g = lane >> 2, m = lane & 3;
    const int r0 = blockIdx.x * 64 + wid * 16 + g;

    // ---- gate B-frag table (f16): kt = wid, wid+4 ----
    #pragma unroll
    for (int t = 0; t < 2; t++) {
        int kt = wid + 4 * t;
        #pragma unroll
        for (int j = 0; j < 4; j++) {
            const float* w0 = Wf_in + (8 * (2 * j)     + g) * 128 + 16 * kt;
            const float* w1 = Wf_in + (8 * (2 * j + 1) + g) * 128 + 16 * kt;
            uint4 q;
            q.x = pkh(w0[2 * m],     w0[2 * m + 1]);
            q.y = pkh(w0[8 + 2 * m], w0[9 + 2 * m]);
            q.z = pkh(w1[2 * m],     w1[2 * m + 1]);
            q.w = pkh(w1[8 + 2 * m], w1[9 + 2 * m]);
            sWf[(kt * 32 + lane) * 5 + j] = q;
        }
    }
    // ---- U frags (hi+lo) ----
    if (wid == 0) {
        #pragma unroll
        for (int kt = 0; kt < 4; kt++) {
            uint32_t hi[2][2], lo[2][2];
            #pragma unroll
            for (int nt = 0; nt < 2; nt++) {
                const float* up = U_in + (8 * nt + g) * 64 + 16 * kt;
                split2(up[2 * m],     up[2 * m + 1], hi[nt][0], lo[nt][0]);
                split2(up[8 + 2 * m], up[9 + 2 * m], hi[nt][1], lo[nt][1]);
            }
            sU[lane * 9 + 2 * kt]     = make_uint4(hi[0][0], hi[0][1], hi[1][0], hi[1][1]);
            sU[lane * 9 + 2 * kt + 1] = make_uint4(lo[0][0], lo[0][1], lo[1][0], lo[1][1]);
        }
    }
    // ---- W frags (hi+lo) ----
    if (wid == 1) {
        #pragma unroll
        for (int j = 0; j < 4; j++) {
            uint32_t hi[2][2], lo[2][2];
            #pragma unroll
            for (int u = 0; u < 2; u++) {
                int n = 8 * (2 * j + u) + g;
                split2(W_in[(2 * m) * 64 + n],     W_in[(2 * m + 1) * 64 + n], hi[u][0], lo[u][0]);
                split2(W_in[(2 * m + 8) * 64 + n], W_in[(2 * m + 9) * 64 + n], hi[u][1], lo[u][1]);
            }
            sW[lane * 9 + 2 * j]     = make_uint4(hi[0][0], hi[0][1], hi[1][0], hi[1][1]);
            sW[lane * 9 + 2 * j + 1] = make_uint4(lo[0][0], lo[0][1], lo[1][0], lo[1][1]);
        }
    }
    // ---- bias f16x2 table ----
    if (wid == 2) {
        int nt = lane >> 2, mm = lane & 3;
        sB16[lane] = pkh(bf_in[8 * nt + 2 * mm], bf_in[8 * nt + 2 * mm + 1]);
    }

    // ---- state: x,v to regs; h*force to SMEM ----
    float xr[32], vr[32];
    uint32_t zr[16];   // packed f16x2: w = z^2 - z  (rden = 1 + w)
    #pragma unroll
    for (int rr = 0; rr < 2; rr++) {
        const size_t base = (size_t)(r0 + 8 * rr) * 64 + 2 * m;
        #pragma unroll
        for (int s = 0; s < 8; s++) {
            float2 t;
            t = *(const float2*)(x_in + base + 8 * s); xr[rr * 16 + 2 * s] = t.x; xr[rr * 16 + 2 * s + 1] = t.y;
            t = *(const float2*)(v_in + base + 8 * s); vr[rr * 16 + 2 * s] = t.x; vr[rr * 16 + 2 * s + 1] = t.y;
            t = *(const float2*)(f_in + base + 8 * s);
            sHF[tid * 34 + rr * 16 + 2 * s]     = HSTEP * t.x;
            sHF[tid * 34 + rr * 16 + 2 * s + 1] = HSTEP * t.y;
        }
    }
    __syncthreads();   // only barrier; loop is barrier-free

    const uint32_t H05 = pkh(0.5f, 0.5f);
    const uint32_t CH2 = pkh(CMU_H, CMU_H);
    float aC[2][4];

    // ---- one g1 k-block (3-way accumulators) ----
    auto g1_block = [&](int kt, float aH[2][4], float aM[2][4], float aL[2][4]){
        uint32_t ah0, ah1, ah2, ah3, al0, al1, al2, al3;
        split2(vr[4 * kt],      vr[4 * kt + 1],  ah0, al0);
        split2(vr[16 + 4 * kt], vr[17 + 4 * kt], ah1, al1);
        split2(vr[4 * kt + 2],  vr[4 * kt + 3],  ah2, al2);
        split2(vr[18 + 4 * kt], vr[19 + 4 * kt], ah3, al3);
        uint4 qh = sU[lane * 9 + 2 * kt];
        uint4 ql = sU[lane * 9 + 2 * kt + 1];
        mma(aH[0], ah0, ah1, ah2, ah3, qh.x, qh.y);
        mma(aH[1], ah0, ah1, ah2, ah3, qh.z, qh.w);
        mma(aM[0], ah0, ah1, ah2, ah3, ql.x, ql.y);
        mma(aM[1], ah0, ah1, ah2, ah3, ql.z, ql.w);
        mma(aL[0], al0, al1, al2, al3, qh.x, qh.y);
        mma(aL[1], al0, al1, al2, al3, qh.z, qh.w);
    };

    auto g1 = [&](){
        float aH[2][4], aM[2][4], aL[2][4];
        #pragma unroll
        for (int nt = 0; nt < 2; nt++)
            #pragma unroll
            for (int k = 0; k < 4; k++) { aH[nt][k] = 0.f; aM[nt][k] = 0.f; aL[nt][k] = 0.f; }
        #pragma unroll
        for (int kt = 0; kt < 4; kt++) g1_block(kt, aH, aM, aL);
        #pragma unroll
        for (int nt = 0; nt < 2; nt++)
            #pragma unroll
            for (int k = 0; k < 4; k++) aC[nt][k] = aH[nt][k] + aM[nt][k] + aL[nt][k];
    };

    // ---- fused: f16 gate GEMM (+ optional g1), sin/cos interleaved ----
    auto fused_gate = [&](bool with_g1){
        uint32_t gc[8][2];
        #pragma unroll
        for (int nt = 0; nt < 8; nt++) { gc[nt][0] = 0u; gc[nt][1] = 0u; }
        float aH[2][4], aM[2][4], aL[2][4];
        if (with_g1) {
            #pragma unroll
            for (int nt = 0; nt < 2; nt++)
                #pragma unroll
                for (int k = 0; k < 4; k++) { aH[nt][k] = 0.f; aM[nt][k] = 0.f; aL[nt][k] = 0.f; }
        }
        #pragma unroll
        for (int kt = 0; kt < 4; kt++) {
            float s0, c0, s1, c1;
            uint32_t a0, a1, a2, a3, c0p, c1p, c2p, c3p;
            __sincosf(xr[4 * kt],      &s0, &c0);
            __sincosf(xr[4 * kt + 1],  &s1, &c1);
            a0 = pkh(s0, s1); c0p = pkh(c0, c1);
            __sincosf(xr[16 + 4 * kt], &s0, &c0);
            __sincosf(xr[17 + 4 * kt], &s1, &c1);
            a1 = pkh(s0, s1); c1p = pkh(c0, c1);
            __sincosf(xr[4 * kt + 2],  &s0, &c0);
            __sincosf(xr[4 * kt + 3],  &s1, &c1);
            a2 = pkh(s0, s1); c2p = pkh(c0, c1);
            __sincosf(xr[18 + 4 * kt], &s0, &c0);
            __sincosf(xr[19 + 4 * kt], &s1, &c1);
            a3 = pkh(s0, s1); c3p = pkh(c0, c1);
            #pragma unroll
            for (int j = 0; j < 4; j++) {
                uint4 qs = sWf[(kt * 32 + lane) * 5 + j];
                mmah(gc[2 * j],     a0, a1, a2, a3, qs.x, qs.y);
                mmah(gc[2 * j + 1], a0, a1, a2, a3, qs.z, qs.w);
                uint4 qc = sWf[((kt + 4) * 32 + lane) * 5 + j];
                mmah(gc[2 * j],     c0p, c1p, c2p, c3p, qc.x, qc.y);
                mmah(gc[2 * j + 1], c0p, c1p, c2p, c3p, qc.z, qc.w);
            }
            if (with_g1) g1_block(kt, aH, aM, aL);
        }
        if (with_g1) {
            #pragma unroll
            for (int nt = 0; nt < 2; nt++)
                #pragma unroll
                for (int k = 0; k < 4; k++) aC[nt][k] = aH[nt][k] + aM[nt][k] + aL[nt][k];
        }
        #pragma unroll
        for (int nt = 0; nt < 8; nt++) {
            uint32_t b2 = sB16[nt * 4 + m];
            #pragma unroll
            for (int rr = 0; rr < 2; rr++) {
                uint32_t gb = hadd2(gc[nt][rr], b2);
                uint32_t th = htanh2(hmul2(gb, H05));
                uint32_t z  = hfma2(th, CH2, CH2);
                zr[2 * nt + rr] = hfma2(z, z, hneg2(z));   // z^2 - z
            }
        }
    };

    // ---- g2 + state update, fused per n-tile ----
    auto g2half = [&](bool first){
        uint32_t h0, h1, h2, h3, l0, l1, l2, l3;
        split2(aC[0][0] * aC[0][0], aC[0][1] * aC[0][1], h0, l0);
        split2(aC[0][2] * aC[0][2], aC[0][3] * aC[0][3], h1, l1);
        split2(aC[1][0] * aC[1][0], aC[1][1] * aC[1][1], h2, l2);
        split2(aC[1][2] * aC[1][2], aC[1][3] * aC[1][3], h3, l3);
        #pragma unroll
        for (int j = 0; j < 4; j++) {
            uint4 qh = sW[lane * 9 + 2 * j];
            uint4 ql = sW[lane * 9 + 2 * j + 1];
            #pragma unroll
            for (int u = 0; u < 2; u++) {
                int nt = 2 * j + u;
                uint32_t bh0 = u ? qh.z : qh.x, bh1 = u ? qh.w : qh.y;
                uint32_t bl0 = u ? ql.z : ql.x, bl1 = u ? ql.w : ql.y;
                float gm[4] = {0.f, 0.f, 0.f, 0.f};
                mma(gm, h0, h1, h2, h3, bh0, bh1);
                mma(gm, h0, h1, h2, h3, bl0, bl1);
                mma(gm, l0, l1, l2, l3, bh0, bh1);
                float2 w0 = h2f2(zr[2 * nt]);
                float2 w1 = h2f2(zr[2 * nt + 1]);
                float2 hf0 = *(const float2*)&sHF[tid * 34 + 2 * nt];
                float2 hf1 = *(const float2*)&sHF[tid * 34 + 16 + 2 * nt];
                int i0 = 2 * nt, i1 = 2 * nt + 1, i2 = 16 + 2 * nt, i3 = 17 + 2 * nt;
                float t0 = fmaf(-HSTEP, gm[0], vr[i0] + hf0.x);
                float t1 = fmaf(-HSTEP, gm[1], vr[i1] + hf0.y);
                float t2 = fmaf(-HSTEP, gm[2], vr[i2] + hf1.x);
                float t3 = fmaf(-HSTEP, gm[3], vr[i3] + hf1.y);
                vr[i0] = fmaf(t0, w0.x, t0);
                vr[i1] = fmaf(t1, w0.y, t1);
                vr[i2] = fmaf(t2, w1.x, t2);
                vr[i3] = fmaf(t3, w1.y, t3);
                if (first) {
                    xr[i0] = fmaf(DT_EFF, vr[i0], xr[i0]);
                    xr[i1] = fmaf(DT_EFF, vr[i1], xr[i1]);
                    xr[i2] = fmaf(DT_EFF, vr[i2], xr[i2]);
                    xr[i3] = fmaf(DT_EFF, vr[i3], xr[i3]);
                }
            }
        }
    };

    // ---- initial friction at x0 ----
    fused_gate(false);

    // ---- main loop (barrier-free) ----
    const int steps = steps_ptr[0];
    for (int s = 0; s < steps; s++) {
        g1();                 // a(v)
        g2half(true);         // v_half, x update  (rden from old x)
        fused_gate(true);     // mu(x_new) || a(v_half)
        g2half(false);        // final v
    }

    // ---- output: wrap x, write x then v ----
    #pragma unroll
    for (int rr = 0; rr < 2; rr++) {
        const size_t base = (size_t)(r0 + 8 * rr) * 64 + 2 * m;
        #pragma unroll
        for (int s = 0; s < 8; s++) {
            float X0 = xr[rr * 16 + 2 * s], X1 = xr[rr * 16 + 2 * s + 1];
            float2 qx;
            qx.x = fmaf(-TWO_PI, rintf(X0 * INV_TWO_PI), X0);
            qx.y = fmaf(-TWO_PI, rintf(X1 * INV_TWO_PI), X1);
            *(float2*)(out + base + 8 * s) = qx;
            float2 qv = make_float2(vr[rr * 16 + 2 * s], vr[rr * 16 + 2 * s + 1]);
            *(float2*)(out + (size_t)Btot * 64 + base + 8 * s) = qv;
        }
    }
}

extern "C" void kernel_launch(void* const* d_in, const int* in_sizes, int n_in,
                              void* d_out, int out_size)
{
    const float* x  = (const float*)d_in[0];
    const float* v  = (const float*)d_in[1];
    const float* f  = (const float*)d_in[2];
    const float* U  = (const float*)d_in[3];
    const float* W  = (const float*)d_in[4];
    const float* Wf = (const float*)d_in[5];
    const float* bf = (const float*)d_in[6];
    const int* steps = (const int*)d_in[7];

    float* out = (float*)d_out;
    const int Btot = in_sizes[0] / 64;     // 262144
    const int blocks = Btot / 64;          // 4096

    leapfrog_r6_kernel<<<blocks, THREADS>>>(x, v, f, U, W, Wf, bf, steps, out, Btot);
}

// round 7
// speedup vs baseline: 1.0900x; 1.0900x over previous
#include <cuda_runtime.h>
#include <stdint.h>

constexpr int THREADS = 128;
constexpr float HSTEP  = 0.05f;     // 0.5 * dt_eff
constexpr float DT_EFF = 0.1f;
constexpr float CMU_H  = 0.00125f;  // 0.5 * h * FRICTION_SCALE
constexpr float TWO_PI     = 6.2831853071795864769f;
constexpr float INV_TWO_PI = 0.15915494309189533577f;

// ---------------- helpers ----------------
__device__ __forceinline__ uint32_t bf2(float lo, float hi){
    uint32_t r; asm("cvt.rn.bf16x2.f32 %0, %1, %2;" : "=r"(r) : "f"(hi), "f"(lo)); return r;
}
__device__ __forceinline__ void split2(float x0, float x1, uint32_t& hi, uint32_t& lo){
    hi = bf2(x0, x1);
    float h0 = __uint_as_float(hi << 16);
    float h1 = __uint_as_float(hi & 0xFFFF0000u);
    lo = bf2(x0 - h0, x1 - h1);
}
__device__ __forceinline__ uint32_t pkh(float lo, float hi){
    uint32_t r; asm("cvt.rn.f16x2.f32 %0, %1, %2;" : "=r"(r) : "f"(hi), "f"(lo)); return r;
}
__device__ __forceinline__ uint32_t hadd2(uint32_t a, uint32_t b){
    uint32_t r; asm("add.rn.f16x2 %0, %1, %2;" : "=r"(r) : "r"(a), "r"(b)); return r;
}
__device__ __forceinline__ uint32_t hmul2(uint32_t a, uint32_t b){
    uint32_t r; asm("mul.rn.f16x2 %0, %1, %2;" : "=r"(r) : "r"(a), "r"(b)); return r;
}
__device__ __forceinline__ uint32_t hfma2(uint32_t a, uint32_t b, uint32_t c){
    uint32_t r; asm("fma.rn.f16x2 %0, %1, %2, %3;" : "=r"(r) : "r"(a), "r"(b), "r"(c)); return r;
}
__device__ __forceinline__ uint32_t htanh2(uint32_t a){
    uint32_t r; asm("tanh.approx.f16x2 %0, %1;" : "=r"(r) : "r"(a)); return r;
}
__device__ __forceinline__ uint32_t hneg2(uint32_t a){
    uint32_t r; asm("neg.f16x2 %0, %1;" : "=r"(r) : "r"(a)); return r;
}
__device__ __forceinline__ float2 h2f2(uint32_t h){
    float2 r;
    asm("{ .reg .f16 lo, hi; mov.b32 {lo, hi}, %2; cvt.f32.f16 %0, lo; cvt.f32.f16 %1, hi; }"
        : "=f"(r.x), "=f"(r.y) : "r"(h));
    return r;
}
// bf16 x bf16 -> f32 accum
__device__ __forceinline__ void mma(float* c, uint32_t a0, uint32_t a1, uint32_t a2, uint32_t a3,
                                    uint32_t b0, uint32_t b1){
    asm("mma.sync.aligned.m16n8k16.row.col.f32.bf16.bf16.f32 "
        "{%0,%1,%2,%3}, {%4,%5,%6,%7}, {%8,%9}, {%0,%1,%2,%3};"
        : "+f"(c[0]), "+f"(c[1]), "+f"(c[2]), "+f"(c[3])
        : "r"(a0), "r"(a1), "r"(a2), "r"(a3), "r"(b0), "r"(b1));
}
// f16 x f16 -> f16 accum (2x rate, 2-reg C)
__device__ __forceinline__ void mmah(uint32_t* c, uint32_t a0, uint32_t a1, uint32_t a2, uint32_t a3,
                                     uint32_t b0, uint32_t b1){
    asm("mma.sync.aligned.m16n8k16.row.col.f16.f16.f16.f16 "
        "{%0,%1}, {%2,%3,%4,%5}, {%6,%7}, {%0,%1};"
        : "+r"(c[0]), "+r"(c[1])
        : "r"(a0), "r"(a1), "r"(a2), "r"(a3), "r"(b0), "r"(b1));
}

// =====================================================================
// Warp owns 16 rows, full 64 cols. Thread (g=lane>>2, m=lane&3) owns rows
// {g, g+8}, cols 8s+2m+e; state idx = rr*16 + 2s + e. Matches mma A/C
// fragment layouts; main loop is barrier-free.
// =====================================================================
__global__ void __launch_bounds__(THREADS, 2)
leapfrog_r7_kernel(const float* __restrict__ x_in, const float* __restrict__ v_in,
                   const float* __restrict__ f_in, const float* __restrict__ U_in,
                   const float* __restrict__ W_in, const float* __restrict__ Wf_in,
                   const float* __restrict__ bf_in, const int* __restrict__ steps_ptr,
                   float* __restrict__ out, int Btot)
{
    __shared__ uint4 sWf[8 * 32 * 5];        // gate B-frags f16 [kt][lane][4j + pad]
    __shared__ uint4 sU[32 * 9];             // U frags [lane][2*kt + (0:hi,1:lo)]
    __shared__ uint4 sW[32 * 9];             // W frags [lane][2*j  + (0:hi,1:lo)]
    __shared__ uint32_t sB16[32];            // bias f16x2 [nt*4+m]
    __shared__ float sHF[128 * 34];          // h*force per thread, stride 34

    const int tid = threadIdx.x, wid = tid >> 5, lane = tid & 31;
    const int g = lane >> 2, m = lane & 3;
    const int r0 = blockIdx.x * 64 + wid * 16 + g;

    // ---- gate B-frag table (f16): kt = wid, wid+4 ----
    #pragma unroll
    for (int t = 0; t < 2; t++) {
        int kt = wid + 4 * t;
        #pragma unroll
        for (int j = 0; j < 4; j++) {
            const float* w0 = Wf_in + (8 * (2 * j)     + g) * 128 + 16 * kt;
            const float* w1 = Wf_in + (8 * (2 * j + 1) + g) * 128 + 16 * kt;
            uint4 q;
            q.x = pkh(w0[2 * m],     w0[2 * m + 1]);
            q.y = pkh(w0[8 + 2 * m], w0[9 + 2 * m]);
            q.z = pkh(w1[2 * m],     w1[2 * m + 1]);
            q.w = pkh(w1[8 + 2 * m], w1[9 + 2 * m]);
            sWf[(kt * 32 + lane) * 5 + j] = q;
        }
    }
    // ---- U frags (hi+lo) ----
    if (wid == 0) {
        #pragma unroll
        for (int kt = 0; kt < 4; kt++) {
            uint32_t hi[2][2], lo[2][2];
            #pragma unroll
            for (int nt = 0; nt < 2; nt++) {
                const float* up = U_in + (8 * nt + g) * 64 + 16 * kt;
                split2(up[2 * m],     up[2 * m + 1], hi[nt][0], lo[nt][0]);
                split2(up[8 + 2 * m], up[9 + 2 * m], hi[nt][1], lo[nt][1]);
            }
            sU[lane * 9 + 2 * kt]     = make_uint4(hi[0][0], hi[0][1], hi[1][0], hi[1][1]);
            sU[lane * 9 + 2 * kt + 1] = make_uint4(lo[0][0], lo[0][1], lo[1][0], lo[1][1]);
        }
    }
    // ---- W frags (hi+lo) ----
    if (wid == 1) {
        #pragma unroll
        for (int j = 0; j < 4; j++) {
            uint32_t hi[2][2], lo[2][2];
            #pragma unroll
            for (int u = 0; u < 2; u++) {
                int n = 8 * (2 * j + u) + g;
                split2(W_in[(2 * m) * 64 + n],     W_in[(2 * m + 1) * 64 + n], hi[u][0], lo[u][0]);
                split2(W_in[(2 * m + 8) * 64 + n], W_in[(2 * m + 9) * 64 + n], hi[u][1], lo[u][1]);
            }
            sW[lane * 9 + 2 * j]     = make_uint4(hi[0][0], hi[0][1], hi[1][0], hi[1][1]);
            sW[lane * 9 + 2 * j + 1] = make_uint4(lo[0][0], lo[0][1], lo[1][0], lo[1][1]);
        }
    }
    // ---- bias f16x2 table ----
    if (wid == 2) {
        int nt = lane >> 2, mm = lane & 3;
        sB16[lane] = pkh(bf_in[8 * nt + 2 * mm], bf_in[8 * nt + 2 * mm + 1]);
    }

    // ---- state: x,v to regs; h*force to SMEM ----
    float xr[32], vr[32];
    uint32_t zr[16];   // packed f16x2: w = z^2 - z  (rden = 1 + w)
    #pragma unroll
    for (int rr = 0; rr < 2; rr++) {
        const size_t base = (size_t)(r0 + 8 * rr) * 64 + 2 * m;
        #pragma unroll
        for (int s = 0; s < 8; s++) {
            float2 t;
            t = *(const float2*)(x_in + base + 8 * s); xr[rr * 16 + 2 * s] = t.x; xr[rr * 16 + 2 * s + 1] = t.y;
            t = *(const float2*)(v_in + base + 8 * s); vr[rr * 16 + 2 * s] = t.x; vr[rr * 16 + 2 * s + 1] = t.y;
            t = *(const float2*)(f_in + base + 8 * s);
            sHF[tid * 34 + rr * 16 + 2 * s]     = HSTEP * t.x;
            sHF[tid * 34 + rr * 16 + 2 * s + 1] = HSTEP * t.y;
        }
    }
    __syncthreads();   // only barrier; loop is barrier-free

    const uint32_t H05 = pkh(0.5f, 0.5f);
    const uint32_t CH2 = pkh(CMU_H, CMU_H);
    float aC[2][4];

    // ---- one g1 k-block (3-way accumulators) ----
    auto g1_block = [&](int kt, float aH[2][4], float aM[2][4], float aL[2][4]){
        uint32_t ah0, ah1, ah2, ah3, al0, al1, al2, al3;
        split2(vr[4 * kt],      vr[4 * kt + 1],  ah0, al0);
        split2(vr[16 + 4 * kt], vr[17 + 4 * kt], ah1, al1);
        split2(vr[4 * kt + 2],  vr[4 * kt + 3],  ah2, al2);
        split2(vr[18 + 4 * kt], vr[19 + 4 * kt], ah3, al3);
        uint4 qh = sU[lane * 9 + 2 * kt];
        uint4 ql = sU[lane * 9 + 2 * kt + 1];
        mma(aH[0], ah0, ah1, ah2, ah3, qh.x, qh.y);
        mma(aH[1], ah0, ah1, ah2, ah3, qh.z, qh.w);
        mma(aM[0], ah0, ah1, ah2, ah3, ql.x, ql.y);
        mma(aM[1], ah0, ah1, ah2, ah3, ql.z, ql.w);
        mma(aL[0], al0, al1, al2, al3, qh.x, qh.y);
        mma(aL[1], al0, al1, al2, al3, qh.z, qh.w);
    };

    auto g1 = [&](){
        float aH[2][4], aM[2][4], aL[2][4];
        #pragma unroll
        for (int nt = 0; nt < 2; nt++)
            #pragma unroll
            for (int k = 0; k < 4; k++) { aH[nt][k] = 0.f; aM[nt][k] = 0.f; aL[nt][k] = 0.f; }
        #pragma unroll
        for (int kt = 0; kt < 4; kt++) g1_block(kt, aH, aM, aL);
        #pragma unroll
        for (int nt = 0; nt < 2; nt++)
            #pragma unroll
            for (int k = 0; k < 4; k++) aC[nt][k] = aH[nt][k] + aM[nt][k] + aL[nt][k];
    };

    // ---- fused: f16 gate GEMM (+ optional g1), sin/cos interleaved ----
    auto fused_gate = [&](bool with_g1){
        uint32_t gc[8][2];
        #pragma unroll
        for (int nt = 0; nt < 8; nt++) { gc[nt][0] = 0u; gc[nt][1] = 0u; }
        float aH[2][4], aM[2][4], aL[2][4];
        if (with_g1) {
            #pragma unroll
            for (int nt = 0; nt < 2; nt++)
                #pragma unroll
                for (int k = 0; k < 4; k++) { aH[nt][k] = 0.f; aM[nt][k] = 0.f; aL[nt][k] = 0.f; }
        }
        #pragma unroll
        for (int kt = 0; kt < 4; kt++) {
            float s0, c0, s1, c1;
            uint32_t a0, a1, a2, a3, c0p, c1p, c2p, c3p;
            __sincosf(xr[4 * kt],      &s0, &c0);
            __sincosf(xr[4 * kt + 1],  &s1, &c1);
            a0 = pkh(s0, s1); c0p = pkh(c0, c1);
            __sincosf(xr[16 + 4 * kt], &s0, &c0);
            __sincosf(xr[17 + 4 * kt], &s1, &c1);
            a1 = pkh(s0, s1); c1p = pkh(c0, c1);
            __sincosf(xr[4 * kt + 2],  &s0, &c0);
            __sincosf(xr[4 * kt + 3],  &s1, &c1);
            a2 = pkh(s0, s1); c2p = pkh(c0, c1);
            __sincosf(xr[18 + 4 * kt], &s0, &c0);
            __sincosf(xr[19 + 4 * kt], &s1, &c1);
            a3 = pkh(s0, s1); c3p = pkh(c0, c1);
            #pragma unroll
            for (int j = 0; j < 4; j++) {
                uint4 qs = sWf[(kt * 32 + lane) * 5 + j];
                mmah(gc[2 * j],     a0, a1, a2, a3, qs.x, qs.y);
                mmah(gc[2 * j + 1], a0, a1, a2, a3, qs.z, qs.w);
                uint4 qc = sWf[((kt + 4) * 32 + lane) * 5 + j];
                mmah(gc[2 * j],     c0p, c1p, c2p, c3p, qc.x, qc.y);
                mmah(gc[2 * j + 1], c0p, c1p, c2p, c3p, qc.z, qc.w);
            }
            if (with_g1) g1_block(kt, aH, aM, aL);
        }
        if (with_g1) {
            #pragma unroll
            for (int nt = 0; nt < 2; nt++)
                #pragma unroll
                for (int k = 0; k < 4; k++) aC[nt][k] = aH[nt][k] + aM[nt][k] + aL[nt][k];
        }
        #pragma unroll
        for (int nt = 0; nt < 8; nt++) {
            uint32_t b2 = sB16[nt * 4 + m];
            #pragma unroll
            for (int rr = 0; rr < 2; rr++) {
                uint32_t gb = hadd2(gc[nt][rr], b2);
                uint32_t th = htanh2(hmul2(gb, H05));
                uint32_t z  = hfma2(th, CH2, CH2);
                zr[2 * nt + rr] = hfma2(z, z, hneg2(z));   // z^2 - z
            }
        }
    };

    // ---- g2 + state update, fused per n-tile ----
    auto g2half = [&](bool first){
        uint32_t h0, h1, h2, h3, l0, l1, l2, l3;
        split2(aC[0][0] * aC[0][0], aC[0][1] * aC[0][1], h0, l0);
        split2(aC[0][2] * aC[0][2], aC[0][3] * aC[0][3], h1, l1);
        split2(aC[1][0] * aC[1][0], aC[1][1] * aC[1][1], h2, l2);
        split2(aC[1][2] * aC[1][2], aC[1][3] * aC[1][3], h3, l3);
        #pragma unroll
        for (int j = 0; j < 4; j++) {
            uint4 qh = sW[lane * 9 + 2 * j];
            uint4 ql = sW[lane * 9 + 2 * j + 1];
            #pragma unroll
            for (int u = 0; u < 2; u++) {
                int nt = 2 * j + u;
                uint32_t bh0 = u ? qh.z : qh.x, bh1 = u ? qh.w : qh.y;
                uint32_t bl0 = u ? ql.z : ql.x, bl1 = u ? ql.w : ql.y;
                float gm[4] = {0.f, 0.f, 0.f, 0.f};
                mma(gm, h0, h1, h2, h3, bh0, bh1);
                mma(gm, h0, h1, h2, h3, bl0, bl1);
                mma(gm, l0, l1, l2, l3, bh0, bh1);
                float2 w0 = h2f2(zr[2 * nt]);
                float2 w1 = h2f2(zr[2 * nt + 1]);
                float2 hf0 = *(const float2*)&sHF[tid * 34 + 2 * nt];
                float2 hf1 = *(const float2*)&sHF[tid * 34 + 16 + 2 * nt];
                int i0 = 2 * nt, i1 = 2 * nt + 1, i2 = 16 + 2 * nt, i3 = 17 + 2 * nt;
                float t0 = fmaf(-HSTEP, gm[0], vr[i0] + hf0.x);
                float t1 = fmaf(-HSTEP, gm[1], vr[i1] + hf0.y);
                float t2 = fmaf(-HSTEP, gm[2], vr[i2] + hf1.x);
                float t3 = fmaf(-HSTEP, gm[3], vr[i3] + hf1.y);
                vr[i0] = fmaf(t0, w0.x, t0);
                vr[i1] = fmaf(t1, w0.y, t1);
                vr[i2] = fmaf(t2, w1.x, t2);
                vr[i3] = fmaf(t3, w1.y, t3);
                if (first) {
                    xr[i0] = fmaf(DT_EFF, vr[i0], xr[i0]);
                    xr[i1] = fmaf(DT_EFF, vr[i1], xr[i1]);
                    xr[i2] = fmaf(DT_EFF, vr[i2], xr[i2]);
                    xr[i3] = fmaf(DT_EFF, vr[i3], xr[i3]);
                }
            }
        }
    };

    // ---- initial friction at x0 ----
    fused_gate(false);

    // ---- main loop (barrier-free) ----
    const int steps = steps_ptr[0];
    for (int s = 0; s < steps; s++) {
        g1();                 // a(v)
        g2half(true);         // v_half, x update  (rden from old x)
        fused_gate(true);     // mu(x_new) || a(v_half)
        g2half(false);        // final v
    }

    // ---- output: wrap x, write x then v ----
    #pragma unroll
    for (int rr = 0; rr < 2; rr++) {
        const size_t base = (size_t)(r0 + 8 * rr) * 64 + 2 * m;
        #pragma unroll
        for (int s = 0; s < 8; s++) {
            float X0 = xr[rr * 16 + 2 * s], X1 = xr[rr * 16 + 2 * s + 1];
            float2 qx;
            qx.x = fmaf(-TWO_PI, rintf(X0 * INV_TWO_PI), X0);
            qx.y = fmaf(-TWO_PI, rintf(X1 * INV_TWO_PI), X1);
            *(float2*)(out + base + 8 * s) = qx;
            float2 qv = make_float2(vr[rr * 16 + 2 * s], vr[rr * 16 + 2 * s + 1]);
            *(float2*)(out + (size_t)Btot * 64 + base + 8 * s) = qv;
        }
    }
}

extern "C" void kernel_launch(void* const* d_in, const int* in_sizes, int n_in,
                              void* d_out, int out_size)
{
    const float* x  = (const float*)d_in[0];
    const float* v  = (const float*)d_in[1];
    const float* f  = (const float*)d_in[2];
    const float* U  = (const float*)d_in[3];
    const float* W  = (const float*)d_in[4];
    const float* Wf = (const float*)d_in[5];
    const float* bf = (const float*)d_in[6];
    const int* steps = (const int*)d_in[7];

    float* out = (float*)d_out;
    const int Btot = in_sizes[0] / 64;     // 262144
    const int blocks = Btot / 64;          // 4096

    leapfrog_r7_kernel<<<blocks, THREADS>>>(x, v, f, U, W, Wf, bf, steps, out, Btot);
}